// round 13
// baseline (speedup 1.0000x reference)
#include <cuda_runtime.h>

// Problem: x[32,64,32,32] f32, gamma/beta [16,64], out [32, 16*64, 32, 32] f32
#define B_       32
#define C_       64
#define HW4_     256                 // 32*32 in float4 units
#define N_       16
#define NPLANES_ (B_ * C_)           // 2048
#define GRP_     4                   // batch groups in reduce
#define BPG_     (B_ / GRP_)         // 8 batches per group
#define PPB_     4                   // planes per apply block
#define APPLY_GRID_ (NPLANES_ / PPB_) // 512
#define INV_CNT  (1.0f / 32768.0f)   // 1/(B*H*W)

// Scratch (static device globals; no allocation). Layout: [g*C + c]
__device__ float g_psum[GRP_ * C_];
__device__ float g_psq [GRP_ * C_];

// ---------------------------------------------------------------------------
// Kernel 1: partial sums. 256 blocks = (g in 0..3) x (c in 0..63).
// Each block covers 8 full (b,c) planes of one channel: 256 threads x
// 8 independent float4 loads (MLP=8) -> latency hidden.
// ---------------------------------------------------------------------------
__global__ __launch_bounds__(256) void reduce_kernel(const float4* __restrict__ x4) {
    const int c = blockIdx.x & (C_ - 1);
    const int g = blockIdx.x >> 6;           // 0..3
    const int t = threadIdx.x;               // 0..255 -> one float4 per plane

    float s = 0.f, q = 0.f;
    #pragma unroll
    for (int j = 0; j < BPG_; j++) {
        const int b = g * BPG_ + j;
        const float4 v = __ldg(&x4[(b * C_ + c) * HW4_ + t]);  // coalesced
        s += v.x + v.y + v.z + v.w;
        q += v.x*v.x + v.y*v.y + v.z*v.z + v.w*v.w;
    }

    #pragma unroll
    for (int o = 16; o > 0; o >>= 1) {
        s += __shfl_down_sync(0xFFFFFFFFu, s, o);
        q += __shfl_down_sync(0xFFFFFFFFu, q, o);
    }
    __shared__ float ss[8], qq[8];
    const int w = t >> 5;
    if ((t & 31) == 0) { ss[w] = s; qq[w] = q; }
    __syncthreads();
    if (t == 0) {
        float S = 0.f, Q = 0.f;
        #pragma unroll
        for (int i = 0; i < 8; i++) { S += ss[i]; Q += qq[i]; }
        g_psum[blockIdx.x] = S;   // blockIdx.x == g*C + c
        g_psq [blockIdx.x] = Q;
    }
}

// ---------------------------------------------------------------------------
// Kernel 2: apply, barrier-free, 4 planes per block (same channel c).
// Front-batch 4 independent x loads (MLP=4), finalize channel stats ONCE
// per warp (shuffles overlap the load latency), then stream 64 FMA'd
// float4 __stcs stores per thread. No __syncthreads, no smem.
// Grid 512 -> ~3.5 block-waves/SM, so load latency is rarely re-exposed.
// ---------------------------------------------------------------------------
__global__ __launch_bounds__(256) void apply_kernel(const float4* __restrict__ x4,
                                                    const float* __restrict__ gamma,
                                                    const float* __restrict__ beta,
                                                    float4* __restrict__ out4) {
    const int c    = blockIdx.x & (C_ - 1);
    const int b0   = blockIdx.x >> 6;        // 0..7
    const int t    = threadIdx.x;            // 0..255
    const int lane = t & 31;

    // Front-batched independent loads: planes (b0 + 8k, c), k = 0..3.
    float4 v[PPB_];
    #pragma unroll
    for (int k = 0; k < PPB_; k++) {
        const int b = b0 + 8 * k;
        v[k] = __ldg(&x4[(b * C_ + c) * HW4_ + t]);   // L2-resident after reduce
    }

    // --- per-warp finalize (once per warp, overlapped with loads) ---
    // lanes 0..3 load psum[g][c], lanes 4..7 load psq[g][c]; butterfly-sum.
    float pv = 0.f;
    if (lane < 8) {
        pv = (lane < 4) ? __ldg(&g_psum[lane * C_ + c])
                        : __ldg(&g_psq [(lane - 4) * C_ + c]);
    }
    pv += __shfl_xor_sync(0xFFFFFFFFu, pv, 1);
    pv += __shfl_xor_sync(0xFFFFFFFFu, pv, 2);
    const float s   = __shfl_sync(0xFFFFFFFFu, pv, 0);   // total sum
    const float q   = __shfl_sync(0xFFFFFFFFu, pv, 4);   // total sumsq
    const float mean = s * INV_CNT;
    const float var  = fmaf(-mean, mean, q * INV_CNT);   // biased var
    const float inv  = rsqrtf(var + 1e-5f);

    // lanes 0..15 own branch n = lane: fold gamma/beta into (sgv, sbv)
    float sgv = 0.f, sbv = 0.f;
    if (lane < N_) {
        const float ga = __ldg(&gamma[lane * C_ + c]);
        const float be = __ldg(&beta [lane * C_ + c]);
        sgv = ga * inv;
        sbv = fmaf(-sgv, mean, be);
    }

    // Stores: out linear (float4 units) = (b*(N*C) + n*C + c) * HW4 + t
    #pragma unroll
    for (int k = 0; k < PPB_; k++) {
        const int b     = b0 + 8 * k;
        const int obase = (b * (N_ * C_) + c) * HW4_ + t;
        #pragma unroll
        for (int n = 0; n < N_; n++) {
            const float sc = __shfl_sync(0xFFFFFFFFu, sgv, n);
            const float tb = __shfl_sync(0xFFFFFFFFu, sbv, n);
            float4 o;
            o.x = fmaf(sc, v[k].x, tb);
            o.y = fmaf(sc, v[k].y, tb);
            o.z = fmaf(sc, v[k].z, tb);
            o.w = fmaf(sc, v[k].w, tb);
            __stcs(&out4[obase + n * (C_ * HW4_)], o);   // evict-first stream
        }
    }
}

// ---------------------------------------------------------------------------
extern "C" void kernel_launch(void* const* d_in, const int* in_sizes, int n_in,
                              void* d_out, int out_size) {
    const float4* x4    = (const float4*)d_in[0];  // x [32,64,32,32]
    const float*  gamma = (const float*) d_in[1];  // [16,64]
    const float*  beta  = (const float*) d_in[2];  // [16,64]
    float4*       out4  = (float4*)d_out;          // [32,1024,32,32]

    reduce_kernel<<<GRP_ * C_, 256>>>(x4);
    apply_kernel <<<APPLY_GRID_, 256>>>(x4, gamma, beta, out4);
}

// round 14
// speedup vs baseline: 1.1333x; 1.1333x over previous
#include <cuda_runtime.h>

// Problem: x[32,64,32,32] f32, gamma/beta [16,64], out [32, 16*64, 32, 32] f32
#define B_       32
#define C_       64
#define HW4_     256                 // 32*32 in float4 units
#define N_       16
#define NPLANES_ (B_ * C_)           // 2048
#define GRP_     4                   // batch groups in reduce
#define BPG_     (B_ / GRP_)         // 8 batches per group
#define INV_CNT  (1.0f / 32768.0f)   // 1/(B*H*W)

// Scratch (static device globals; no allocation). Layout: [g*C + c]
__device__ float g_psum[GRP_ * C_];
__device__ float g_psq [GRP_ * C_];

// ---------------------------------------------------------------------------
// Kernel 1: partial sums. 256 blocks = (g in 0..3) x (c in 0..63).
// Each block covers 8 full (b,c) planes of one channel: 256 threads x
// 8 independent float4 loads (MLP=8). Triggers programmatic launch of the
// apply kernel at entry so apply's load prologue overlaps this kernel.
// ---------------------------------------------------------------------------
__global__ __launch_bounds__(256) void reduce_kernel(const float4* __restrict__ x4) {
    cudaTriggerProgrammaticLaunchCompletion();   // let apply start launching now

    const int c = blockIdx.x & (C_ - 1);
    const int g = blockIdx.x >> 6;           // 0..3
    const int t = threadIdx.x;               // 0..255 -> one float4 per plane

    float s = 0.f, q = 0.f;
    #pragma unroll
    for (int j = 0; j < BPG_; j++) {
        const int b = g * BPG_ + j;
        const float4 v = __ldg(&x4[(b * C_ + c) * HW4_ + t]);  // coalesced
        s += v.x + v.y + v.z + v.w;
        q += v.x*v.x + v.y*v.y + v.z*v.z + v.w*v.w;
    }

    #pragma unroll
    for (int o = 16; o > 0; o >>= 1) {
        s += __shfl_down_sync(0xFFFFFFFFu, s, o);
        q += __shfl_down_sync(0xFFFFFFFFu, q, o);
    }
    __shared__ float ss[8], qq[8];
    const int w = t >> 5;
    if ((t & 31) == 0) { ss[w] = s; qq[w] = q; }
    __syncthreads();
    if (t == 0) {
        float S = 0.f, Q = 0.f;
        #pragma unroll
        for (int i = 0; i < 8; i++) { S += ss[i]; Q += qq[i]; }
        g_psum[blockIdx.x] = S;   // blockIdx.x == g*C + c
        g_psq [blockIdx.x] = Q;
    }
}

// ---------------------------------------------------------------------------
// Kernel 2: apply (R12 config: 2048 blocks, 1 plane/block, barrier-free).
// PDL: front-issue the x-plane load + gamma/beta loads (independent of the
// reduce), THEN cudaGridDependencySynchronize() before reading partials.
// Per-warp finalize via shuffles; 16 FMA'd float4 __stcs stores per thread.
// ---------------------------------------------------------------------------
__global__ __launch_bounds__(256) void apply_kernel(const float4* __restrict__ x4,
                                                    const float* __restrict__ gamma,
                                                    const float* __restrict__ beta,
                                                    float4* __restrict__ out4) {
    const int bc   = blockIdx.x;         // b*C + c
    const int c    = bc & (C_ - 1);
    const int b    = bc >> 6;
    const int t    = threadIdx.x;        // 0..255
    const int lane = t & 31;

    // ---- prologue: everything that does NOT depend on the reduce ----
    const float4 v = __ldg(&x4[bc * HW4_ + t]);     // big load, issued first

    float ga = 0.f, be = 0.f;
    if (lane < N_) {
        ga = __ldg(&gamma[lane * C_ + c]);
        be = __ldg(&beta [lane * C_ + c]);
    }

    // ---- wait for the reduce grid's writes to be visible ----
    cudaGridDependencySynchronize();

    // per-warp finalize: lanes 0..3 psum[g][c], lanes 4..7 psq[g][c]
    float pv = 0.f;
    if (lane < 8) {
        pv = (lane < 4) ? __ldg(&g_psum[lane * C_ + c])
                        : __ldg(&g_psq [(lane - 4) * C_ + c]);
    }
    pv += __shfl_xor_sync(0xFFFFFFFFu, pv, 1);
    pv += __shfl_xor_sync(0xFFFFFFFFu, pv, 2);
    const float s   = __shfl_sync(0xFFFFFFFFu, pv, 0);   // total sum
    const float q   = __shfl_sync(0xFFFFFFFFu, pv, 4);   // total sumsq
    const float mean = s * INV_CNT;
    const float var  = fmaf(-mean, mean, q * INV_CNT);   // biased var
    const float inv  = rsqrtf(var + 1e-5f);

    float sgv = 0.f, sbv = 0.f;
    if (lane < N_) {
        sgv = ga * inv;
        sbv = fmaf(-sgv, mean, be);
    }

    // out linear (float4 units): (b*(N*C) + n*C + c) * HW4 + t
    const int obase = (b * (N_ * C_) + c) * HW4_ + t;

    #pragma unroll
    for (int n = 0; n < N_; n++) {
        const float sc = __shfl_sync(0xFFFFFFFFu, sgv, n);
        const float tb = __shfl_sync(0xFFFFFFFFu, sbv, n);
        float4 o;
        o.x = fmaf(sc, v.x, tb);
        o.y = fmaf(sc, v.y, tb);
        o.z = fmaf(sc, v.z, tb);
        o.w = fmaf(sc, v.w, tb);
        __stcs(&out4[obase + n * (C_ * HW4_)], o);       // evict-first stream
    }
}

// ---------------------------------------------------------------------------
extern "C" void kernel_launch(void* const* d_in, const int* in_sizes, int n_in,
                              void* d_out, int out_size) {
    const float4* x4    = (const float4*)d_in[0];  // x [32,64,32,32]
    const float*  gamma = (const float*) d_in[1];  // [16,64]
    const float*  beta  = (const float*) d_in[2];  // [16,64]
    float4*       out4  = (float4*)d_out;          // [32,1024,32,32]

    reduce_kernel<<<GRP_ * C_, 256>>>(x4);

    // Apply launched with programmatic dependence on the reduce (PDL):
    // it begins launching as soon as all reduce blocks hit the trigger,
    // overlapping its load prologue with the reduce + prior-replay drain.
    cudaLaunchConfig_t cfg = {};
    cfg.gridDim  = dim3(NPLANES_);
    cfg.blockDim = dim3(256);
    cfg.dynamicSmemBytes = 0;
    cfg.stream = 0;  // same (legacy default) stream as <<<>>> above
    cudaLaunchAttribute attr[1];
    attr[0].id = cudaLaunchAttributeProgrammaticStreamSerialization;
    attr[0].val.programmaticStreamSerializationAllowed = 1;
    cfg.attrs = attr;
    cfg.numAttrs = 1;
    cudaLaunchKernelEx(&cfg, apply_kernel, x4, gamma, beta, out4);
}